// round 11
// baseline (speedup 1.0000x reference)
#include <cuda_runtime.h>
#include <cstdint>

#define DIMC 64
#define NPIX 512            // 9-bit single-pixel patterns
#define NBINS 4096          // 12-bit pair patterns
#define CHUNKS 6            // 64 rows per block, two 32-row passes
#define IMG 384
#define WORDS 12            // 384 / 32
#define BATCH 32
#define OUTW 65
#define NBLOCKS (BATCH * CHUNKS)   // 192

// Static scratch. g_cnt starts zero; every launch: REDG-accumulated by the 6
// chunk blocks of an image, then read+rezeroed by that image's last finisher
// -> replay-deterministic. g_done: 0 -> 6 arrivals -> reset to 0.
__device__ int      g_cnt[BATCH][NPIX];   // 64 KB
__device__ unsigned g_done[BATCH];

__global__ __launch_bounds__(384, 2) void mono_kernel(
    const float* __restrict__ alpha,
    const float* __restrict__ w, const float* __restrict__ bias,
    const float* __restrict__ gamma, const float* __restrict__ beta,
    const float* __restrict__ mean, const float* __restrict__ var,
    float* __restrict__ out)
{
    __shared__ int      hist[NBINS];              // 16 KB; overlaid by contract
    __shared__ uint32_t bits[2][34][WORDS + 2];   // ~3.8 KB double-buffered
    __shared__ unsigned rank_s;

    int tid   = threadIdx.x;
    int b     = blockIdx.x / CHUNKS;
    int chunk = blockIdx.x % CHUNKS;
    int lane  = tid & 31;
    int warp  = tid >> 5;                         // 0..11 = word column

    for (int i = tid; i < NBINS; i += 384) hist[i] = 0;
    if (tid < 34) {
        bits[0][tid][0] = 0u; bits[0][tid][WORDS + 1] = 0u;
        bits[1][tid][0] = 0u; bits[1][tid][WORDS + 1] = 0u;
    }

    const float* img = alpha + (size_t)b * IMG * IMG;
    int r  = tid / WORDS;    // 0..31 local row (384 = 32*12)
    int wd = tid % WORDS;
    int rowbase0 = chunk * 64;
    int rowbase1 = chunk * 64 + 32;

    // ---- pass 0: batched loads, ballots ----
    float v[34];
#pragma unroll
    for (int row = 0; row < 34; ++row) {
        int g = rowbase0 - 1 + row;
        v[row] = (g >= 0 && g < IMG) ? img[g * IMG + warp * 32 + lane] : 0.0f;
    }
#pragma unroll
    for (int row = 0; row < 34; ++row) {
        uint32_t wb = __ballot_sync(0xffffffffu, ((int)(v[row] * 255.0f)) & 1);
        if (lane == 0) bits[0][row][warp + 1] = wb;
    }
    __syncthreads();

    uint32_t p0 = bits[0][r][wd],     c0 = bits[0][r][wd + 1],     x0 = bits[0][r][wd + 2];
    uint32_t p1 = bits[0][r + 1][wd], c1 = bits[0][r + 1][wd + 1], x1 = bits[0][r + 1][wd + 2];
    uint32_t p2 = bits[0][r + 2][wd], c2 = bits[0][r + 2][wd + 1], x2 = bits[0][r + 2][wd + 2];

    // issue pass-1 loads now (hide DRAM behind pass-0 atomics)
    float u[34];
#pragma unroll
    for (int row = 0; row < 34; ++row) {
        int g = rowbase1 - 1 + row;
        u[row] = (g < IMG) ? img[g * IMG + warp * 32 + lane] : 0.0f;
    }

    // pass-0 shared atomics (16 pairs/thread)
    {
        uint32_t n0 = __funnelshift_r(p0, c0, 31) & 0xF;
        uint32_t n1 = __funnelshift_r(p1, c1, 31) & 0xF;
        uint32_t n2 = __funnelshift_r(p2, c2, 31) & 0xF;
        atomicAdd(&hist[n0 | (n1 << 4) | (n2 << 8)], 1);
    }
#pragma unroll
    for (int k = 1; k < 16; ++k) {
        uint32_t n0 = __funnelshift_r(c0, x0, 2 * k - 1) & 0xF;
        uint32_t n1 = __funnelshift_r(c1, x1, 2 * k - 1) & 0xF;
        uint32_t n2 = __funnelshift_r(c2, x2, 2 * k - 1) & 0xF;
        atomicAdd(&hist[n0 | (n1 << 4) | (n2 << 8)], 1);
    }

    // pass-1 ballots into second buffer
#pragma unroll
    for (int row = 0; row < 34; ++row) {
        uint32_t wb = __ballot_sync(0xffffffffu, ((int)(u[row] * 255.0f)) & 1);
        if (lane == 0) bits[1][row][warp + 1] = wb;
    }
    __syncthreads();

    p0 = bits[1][r][wd];     c0 = bits[1][r][wd + 1];     x0 = bits[1][r][wd + 2];
    p1 = bits[1][r + 1][wd]; c1 = bits[1][r + 1][wd + 1]; x1 = bits[1][r + 1][wd + 2];
    p2 = bits[1][r + 2][wd]; c2 = bits[1][r + 2][wd + 1]; x2 = bits[1][r + 2][wd + 2];

    {
        uint32_t n0 = __funnelshift_r(p0, c0, 31) & 0xF;
        uint32_t n1 = __funnelshift_r(p1, c1, 31) & 0xF;
        uint32_t n2 = __funnelshift_r(p2, c2, 31) & 0xF;
        atomicAdd(&hist[n0 | (n1 << 4) | (n2 << 8)], 1);
    }
#pragma unroll
    for (int k = 1; k < 16; ++k) {
        uint32_t n0 = __funnelshift_r(c0, x0, 2 * k - 1) & 0xF;
        uint32_t n1 = __funnelshift_r(c1, x1, 2 * k - 1) & 0xF;
        uint32_t n2 = __funnelshift_r(c2, x2, 2 * k - 1) & 0xF;
        atomicAdd(&hist[n0 | (n1 << 4) | (n2 << 8)], 1);
    }
    __syncthreads();

    // ---- gather-marginalize 4096 pair bins -> 512 pixel bins, REDG flush ----
    // A side: pattern bits at pair positions {0-2,4-6,8-10}, free {3,7,11};
    // B side: shifted left 1, free {0,4,8}.
    for (int n = tid; n < NPIX; n += 384) {
        uint32_t nb = (n & 7) | ((n & 0x38) << 1) | ((n & 0x1C0) << 2);
        int s = 0;
#pragma unroll
        for (int j = 0; j < 8; ++j) {
            uint32_t off = ((j & 1) << 3) | ((j & 2) << 6) | ((j & 4) << 9);
            s += hist[nb | off];                 // A side
            s += hist[(nb << 1) | (off >> 3)];   // B side
        }
        atomicAdd(&g_cnt[b][n], s);              // REDG, no return
    }

    // ---- arrival handshake: last of 6 chunk blocks contracts ----
    __threadfence();
    __syncthreads();
    if (tid == 0) rank_s = atomicAdd(&g_done[b], 1u);
    __syncthreads();
    if (rank_s != CHUNKS - 1) return;

    if (tid == 0) g_done[b] = 0;                 // reset for next replay
    __threadfence();

    // ======== contract role (one block per image) ========
    float* cnt1 = (float*)hist;                  // [0,512)
    float* T    = (float*)hist + 512;            // 3 x 8 x 64 = 1536
    float* red  = (float*)hist + 2048;           // 6 x 64

    // combined counts (L2-hot), rezero for replay; fold 1/(H*W)
    for (int n = tid; n < NPIX; n += 384) {
        int s = __ldcg(&g_cnt[b][n]);
        __stcg(&g_cnt[b][n], 0);
        cnt1[n] = (float)s * (1.0f / (384.0f * 384.0f));
    }

    // nibble tables: T[r][vv][c] = sum of w[c][3r+k] over set bits k of vv
    for (int i = tid; i < 3 * 8 * DIMC; i += 384) {
        int rr = i >> 9;                         // 0..2
        int vv = (i >> 6) & 7;
        int c  = i & 63;
        float d = 0.f;
#pragma unroll
        for (int k = 0; k < 3; ++k)
            if ((vv >> k) & 1) d += w[c * 9 + rr * 3 + k];
        T[(rr * 8 + vv) * DIMC + c] = d;
    }

    int c = tid & 63;
    int g = tid >> 6;                            // 0..5
    float A = gamma[c] * rsqrtf(var[c] + 1e-5f);
    float cb = (bias[c] - mean[c]) * A + beta[c];
    __syncthreads();

    // 512 bins x 64 ch: 3 conflict-free LDS + relu(bn) + fma per (bin,c)
    float acc = 0.f;
    for (int bin = g; bin < NPIX; bin += 6) {
        float d = T[(bin & 7) * DIMC + c]
                + T[(8  + ((bin >> 3) & 7)) * DIMC + c]
                + T[(16 + (bin >> 6)) * DIMC + c];
        float val = fmaxf(fmaf(A, d, cb), 0.f);
        acc = fmaf(cnt1[bin], val, acc);
    }
    red[g * DIMC + c] = acc;
    __syncthreads();

    if (tid < DIMC) {
        out[b * OUTW + tid] = red[0 * DIMC + tid] + red[1 * DIMC + tid]
                            + red[2 * DIMC + tid] + red[3 * DIMC + tid]
                            + red[4 * DIMC + tid] + red[5 * DIMC + tid];
    }

    // marker column for this image's row (warp 2: one ballot over alpha[0..32))
    if (warp == 2) {
        float av = alpha[lane];
        uint32_t word = __ballot_sync(0xffffffffu, ((int)(av * 255.0f)) & 1);
        if (lane == 0)
            out[b * OUTW + DIMC] = (__brev(word) == 0x41493234u) ? 1.0f : 0.0f;  // 'AI24'
    }
}

// ---------------------------------------------------------------------------
extern "C" void kernel_launch(void* const* d_in, const int* in_sizes, int n_in,
                              void* d_out, int out_size)
{
    const float* alpha  = (const float*)d_in[0];
    const float* conv_w = (const float*)d_in[1];
    const float* conv_b = (const float*)d_in[2];
    const float* bn_g   = (const float*)d_in[3];
    const float* bn_b   = (const float*)d_in[4];
    const float* bn_m   = (const float*)d_in[5];
    const float* bn_v   = (const float*)d_in[6];
    float* out = (float*)d_out;

    mono_kernel<<<NBLOCKS, 384>>>(
        alpha, conv_w, conv_b, bn_g, bn_b, bn_m, bn_v, out);
}

// round 12
// speedup vs baseline: 1.1268x; 1.1268x over previous
#include <cuda_runtime.h>
#include <cstdint>

#define DIMC 64
#define NPIX 512            // 9-bit single-pixel patterns
#define NBINS 4096          // 12-bit pair patterns
#define CHUNKS 6            // 64 rows per hist block, two 32-row passes
#define IMG 384
#define WORDS 12            // 384 / 32
#define BATCH 32
#define OUTW 65
#define HIST_BLOCKS (BATCH * CHUNKS)          // 192
#define NBLOCKS (HIST_BLOCKS + BATCH)         // 224 = 192 hist + 32 waiters (<=296 resident)

// Static scratch. g_cnt zero at load; per launch: REDG-accumulated by 6 hist
// blocks, read + rezeroed by the image's waiter block -> replay-deterministic.
// g_done: 0 -> 6 -> reset to 0 by the waiter.
__device__ int      g_cnt[BATCH][NPIX];   // 64 KB
__device__ unsigned g_done[BATCH];

__global__ __launch_bounds__(384, 2) void mono_kernel(
    const float* __restrict__ alpha,
    const float* __restrict__ w, const float* __restrict__ bias,
    const float* __restrict__ gamma, const float* __restrict__ beta,
    const float* __restrict__ mean, const float* __restrict__ var,
    float* __restrict__ out)
{
    __shared__ int      hist[NBINS];              // 16 KB; waiters reuse as float scratch
    __shared__ uint32_t bits[2][34][WORDS + 2];   // ~3.8 KB

    int tid  = threadIdx.x;
    int lane = tid & 31;
    int warp = tid >> 5;

    // ======================= WAITER / CONTRACT role =======================
    if (blockIdx.x >= HIST_BLOCKS) {
        int b = blockIdx.x - HIST_BLOCKS;         // image

        float* cnt1 = (float*)hist;               // [0,512)
        float* T    = (float*)hist + 512;         // 3 x 8 x 64 = 1536
        float* red  = (float*)hist + 2048;        // 6 x 64

        // ---- prep BEFORE waiting (overlaps with hist phase) ----
        // nibble tables: T[r][vv][c] = sum of w[c][3r+k] over set bits k of vv
        for (int i = tid; i < 3 * 8 * DIMC; i += 384) {
            int rr = i >> 9;                      // 0..2
            int vv = (i >> 6) & 7;
            int c  = i & 63;
            float d = 0.f;
#pragma unroll
            for (int k = 0; k < 3; ++k)
                if ((vv >> k) & 1) d += w[c * 9 + rr * 3 + k];
            T[(rr * 8 + vv) * DIMC + c] = d;
        }
        int c = tid & 63;
        int g = tid >> 6;                         // 0..5
        float A  = gamma[c] * rsqrtf(var[c] + 1e-5f);
        float cb = (bias[c] - mean[c]) * A + beta[c];

        // marker for this image's row (same value for all rows; computed here)
        float marker = 0.f;
        if (warp == 2) {
            float av = alpha[lane];
            uint32_t word = __ballot_sync(0xffffffffu, ((int)(av * 255.0f)) & 1);
            marker = (__brev(word) == 0x41493234u) ? 1.0f : 0.0f;   // 'AI24'
        }
        __syncthreads();                          // T[] ready

        // ---- spin until this image's 6 chunk blocks have flushed ----
        if (tid == 0) {
            volatile unsigned* gd = &g_done[b];
            while (*gd != (unsigned)CHUNKS) __nanosleep(64);
            g_done[b] = 0;                        // reset for next replay
        }
        __syncthreads();
        __threadfence();                          // acquire

        // combined counts (L2-hot), rezero for replay; fold 1/(H*W)
        for (int n = tid; n < NPIX; n += 384) {
            int s = __ldcg(&g_cnt[b][n]);
            __stcg(&g_cnt[b][n], 0);
            cnt1[n] = (float)s * (1.0f / (384.0f * 384.0f));
        }
        __syncthreads();

        // contract: 512 bins x 64 ch, 3 conflict-free LDS + relu(bn) + fma
        float acc = 0.f;
        for (int bin = g; bin < NPIX; bin += 6) {
            float d = T[(bin & 7) * DIMC + c]
                    + T[(8  + ((bin >> 3) & 7)) * DIMC + c]
                    + T[(16 + (bin >> 6)) * DIMC + c];
            float val = fmaxf(fmaf(A, d, cb), 0.f);
            acc = fmaf(cnt1[bin], val, acc);
        }
        red[g * DIMC + c] = acc;
        __syncthreads();

        if (tid < DIMC)
            out[b * OUTW + tid] = red[0 * DIMC + tid] + red[1 * DIMC + tid]
                                + red[2 * DIMC + tid] + red[3 * DIMC + tid]
                                + red[4 * DIMC + tid] + red[5 * DIMC + tid];
        if (warp == 2 && lane == 0)
            out[b * OUTW + DIMC] = marker;
        return;
    }

    // ======================= HIST role =======================
    int b     = blockIdx.x / CHUNKS;
    int chunk = blockIdx.x % CHUNKS;

    for (int i = tid; i < NBINS; i += 384) hist[i] = 0;
    if (tid < 34) {
        bits[0][tid][0] = 0u; bits[0][tid][WORDS + 1] = 0u;
        bits[1][tid][0] = 0u; bits[1][tid][WORDS + 1] = 0u;
    }

    const float* img = alpha + (size_t)b * IMG * IMG;
    int r  = tid / WORDS;    // 0..31 local row (384 = 32*12)
    int wd = tid % WORDS;
    int rowbase0 = chunk * 64;
    int rowbase1 = chunk * 64 + 32;

    // ---- pass 0: batched loads, ballots ----
    float v[34];
#pragma unroll
    for (int row = 0; row < 34; ++row) {
        int g = rowbase0 - 1 + row;
        v[row] = (g >= 0 && g < IMG) ? img[g * IMG + warp * 32 + lane] : 0.0f;
    }
#pragma unroll
    for (int row = 0; row < 34; ++row) {
        uint32_t wb = __ballot_sync(0xffffffffu, ((int)(v[row] * 255.0f)) & 1);
        if (lane == 0) bits[0][row][warp + 1] = wb;
    }
    __syncthreads();

    uint32_t p0 = bits[0][r][wd],     c0 = bits[0][r][wd + 1],     x0 = bits[0][r][wd + 2];
    uint32_t p1 = bits[0][r + 1][wd], c1 = bits[0][r + 1][wd + 1], x1 = bits[0][r + 1][wd + 2];
    uint32_t p2 = bits[0][r + 2][wd], c2 = bits[0][r + 2][wd + 1], x2 = bits[0][r + 2][wd + 2];

    // issue pass-1 loads now (hide DRAM behind pass-0 atomics)
    float u[34];
#pragma unroll
    for (int row = 0; row < 34; ++row) {
        int g = rowbase1 - 1 + row;
        u[row] = (g < IMG) ? img[g * IMG + warp * 32 + lane] : 0.0f;
    }

    // pass-0 shared atomics (16 pairs/thread)
    {
        uint32_t n0 = __funnelshift_r(p0, c0, 31) & 0xF;
        uint32_t n1 = __funnelshift_r(p1, c1, 31) & 0xF;
        uint32_t n2 = __funnelshift_r(p2, c2, 31) & 0xF;
        atomicAdd(&hist[n0 | (n1 << 4) | (n2 << 8)], 1);
    }
#pragma unroll
    for (int k = 1; k < 16; ++k) {
        uint32_t n0 = __funnelshift_r(c0, x0, 2 * k - 1) & 0xF;
        uint32_t n1 = __funnelshift_r(c1, x1, 2 * k - 1) & 0xF;
        uint32_t n2 = __funnelshift_r(c2, x2, 2 * k - 1) & 0xF;
        atomicAdd(&hist[n0 | (n1 << 4) | (n2 << 8)], 1);
    }

    // pass-1 ballots into second buffer
#pragma unroll
    for (int row = 0; row < 34; ++row) {
        uint32_t wb = __ballot_sync(0xffffffffu, ((int)(u[row] * 255.0f)) & 1);
        if (lane == 0) bits[1][row][warp + 1] = wb;
    }
    __syncthreads();

    p0 = bits[1][r][wd];     c0 = bits[1][r][wd + 1];     x0 = bits[1][r][wd + 2];
    p1 = bits[1][r + 1][wd]; c1 = bits[1][r + 1][wd + 1]; x1 = bits[1][r + 1][wd + 2];
    p2 = bits[1][r + 2][wd]; c2 = bits[1][r + 2][wd + 1]; x2 = bits[1][r + 2][wd + 2];

    {
        uint32_t n0 = __funnelshift_r(p0, c0, 31) & 0xF;
        uint32_t n1 = __funnelshift_r(p1, c1, 31) & 0xF;
        uint32_t n2 = __funnelshift_r(p2, c2, 31) & 0xF;
        atomicAdd(&hist[n0 | (n1 << 4) | (n2 << 8)], 1);
    }
#pragma unroll
    for (int k = 1; k < 16; ++k) {
        uint32_t n0 = __funnelshift_r(c0, x0, 2 * k - 1) & 0xF;
        uint32_t n1 = __funnelshift_r(c1, x1, 2 * k - 1) & 0xF;
        uint32_t n2 = __funnelshift_r(c2, x2, 2 * k - 1) & 0xF;
        atomicAdd(&hist[n0 | (n1 << 4) | (n2 << 8)], 1);
    }
    __syncthreads();

    // gather-marginalize 4096 pair bins -> 512 pixel bins, REDG flush.
    // A side: pattern bits at pair positions {0-2,4-6,8-10}, free {3,7,11};
    // B side: shifted left 1, free {0,4,8}.
    for (int n = tid; n < NPIX; n += 384) {
        uint32_t nb = (n & 7) | ((n & 0x38) << 1) | ((n & 0x1C0) << 2);
        int s = 0;
#pragma unroll
        for (int j = 0; j < 8; ++j) {
            uint32_t off = ((j & 1) << 3) | ((j & 2) << 6) | ((j & 4) << 9);
            s += hist[nb | off];                 // A side
            s += hist[(nb << 1) | (off >> 3)];   // B side
        }
        atomicAdd(&g_cnt[b][n], s);              // REDG, no return
    }

    // release: REDs visible before done counter increments
    __threadfence();
    __syncthreads();
    if (tid == 0) atomicAdd(&g_done[b], 1u);
}

// ---------------------------------------------------------------------------
extern "C" void kernel_launch(void* const* d_in, const int* in_sizes, int n_in,
                              void* d_out, int out_size)
{
    const float* alpha  = (const float*)d_in[0];
    const float* conv_w = (const float*)d_in[1];
    const float* conv_b = (const float*)d_in[2];
    const float* bn_g   = (const float*)d_in[3];
    const float* bn_b   = (const float*)d_in[4];
    const float* bn_m   = (const float*)d_in[5];
    const float* bn_v   = (const float*)d_in[6];
    float* out = (float*)d_out;

    mono_kernel<<<NBLOCKS, 384>>>(
        alpha, conv_w, conv_b, bn_g, bn_b, bn_m, bn_v, out);
}

// round 14
// speedup vs baseline: 1.4968x; 1.3283x over previous
#include <cuda_runtime.h>
#include <cstdint>

#define DIMC 64
#define NPIX 512            // 9-bit single-pixel patterns
#define NBINS 4096          // 12-bit pair patterns
#define CHUNKS 8            // 48 rows per hist block, two 24-row passes
#define ROWS_PB 48
#define PASS_ROWS 24
#define LOADS 26            // PASS_ROWS + 2 halo
#define IMG 384
#define WORDS 12            // 384 / 32
#define BATCH 32
#define OUTW 65
#define H_BLOCKS (BATCH * CHUNKS)   // 256

// Static scratch: per-block pair-histogram partials, fully rewritten each launch.
__device__ int g_part[H_BLOCKS * NBINS];   // 4 MB

// ---------------------------------------------------------------------------
// H: pair-pattern histogram. 256 blocks x 384 threads, 48 rows per block in
// two simple (non-pipelined -> no spills) 24-row passes. int4 STG flush.
// ---------------------------------------------------------------------------
__global__ __launch_bounds__(384) void hist_kernel(const float* __restrict__ alpha)
{
    __shared__ uint32_t bits[LOADS][WORDS + 2];   // zero-padded cols
    __shared__ int hist[NBINS];

    int tid   = threadIdx.x;
    int b     = blockIdx.x / CHUNKS;
    int chunk = blockIdx.x % CHUNKS;
    int lane  = tid & 31;
    int warp  = tid >> 5;                          // 0..11 = word column

    for (int i = tid; i < NBINS; i += 384) hist[i] = 0;
    if (tid < LOADS) { bits[tid][0] = 0u; bits[tid][WORDS + 1] = 0u; }

    const float* img = alpha + (size_t)b * IMG * IMG;
    int r  = tid / WORDS;     // 0..31; active for pairs when r < 24
    int wd = tid % WORDS;

#pragma unroll
    for (int pass = 0; pass < 2; ++pass) {
        int rb = chunk * ROWS_PB + pass * PASS_ROWS;

        // batched loads (MLP=26), then ballots
        float v[LOADS];
#pragma unroll
        for (int row = 0; row < LOADS; ++row) {
            int g = rb - 1 + row;
            v[row] = (g >= 0 && g < IMG) ? img[g * IMG + warp * 32 + lane] : 0.0f;
        }
#pragma unroll
        for (int row = 0; row < LOADS; ++row) {
            uint32_t wb = __ballot_sync(0xffffffffu, ((int)(v[row] * 255.0f)) & 1);
            if (lane == 0) bits[row][warp + 1] = wb;
        }
        __syncthreads();

        if (r < PASS_ROWS) {
            uint32_t p0 = bits[r][wd],     c0 = bits[r][wd + 1],     x0 = bits[r][wd + 2];
            uint32_t p1 = bits[r + 1][wd], c1 = bits[r + 1][wd + 1], x1 = bits[r + 1][wd + 2];
            uint32_t p2 = bits[r + 2][wd], c2 = bits[r + 2][wd + 1], x2 = bits[r + 2][wd + 2];

            {   // pair k=0: window straddles previous word
                uint32_t n0 = __funnelshift_r(p0, c0, 31) & 0xF;
                uint32_t n1 = __funnelshift_r(p1, c1, 31) & 0xF;
                uint32_t n2 = __funnelshift_r(p2, c2, 31) & 0xF;
                atomicAdd(&hist[n0 | (n1 << 4) | (n2 << 8)], 1);
            }
#pragma unroll
            for (int k = 1; k < 16; ++k) {
                uint32_t n0 = __funnelshift_r(c0, x0, 2 * k - 1) & 0xF;
                uint32_t n1 = __funnelshift_r(c1, x1, 2 * k - 1) & 0xF;
                uint32_t n2 = __funnelshift_r(c2, x2, 2 * k - 1) & 0xF;
                atomicAdd(&hist[n0 | (n1 << 4) | (n2 << 8)], 1);
            }
        }
        __syncthreads();   // protect bits[] before next pass
    }

    // vectorized flush (STG.128)
    int4* dst = (int4*)(g_part + blockIdx.x * NBINS);
    const int4* src = (const int4*)hist;
    for (int i = tid; i < NBINS / 4; i += 384) dst[i] = src[i];
}

// ---------------------------------------------------------------------------
// R: one block per image, 1024 threads.
//   merge 8 partials (batched int4) -> gather-marginalize 4096 -> 512 ->
//   nibble-table contract (relu(bn(conv)) inline) -> write out row + marker.
// No LUT buffer, no out zero-init, no out atomics.
// ---------------------------------------------------------------------------
__global__ __launch_bounds__(1024) void reduce_kernel(
    const float* __restrict__ alpha,
    const float* __restrict__ w, const float* __restrict__ bias,
    const float* __restrict__ gamma, const float* __restrict__ beta,
    const float* __restrict__ mean, const float* __restrict__ var,
    float* __restrict__ out)
{
    __shared__ int   hist[NBINS];            // 16 KB merged pair histogram
    __shared__ float cnt1[NPIX];             // 2 KB pixel-bin counts
    __shared__ float T[3 * 8 * DIMC];        // 6 KB nibble tables
    __shared__ float red[16 * DIMC];         // 4 KB

    int tid = threadIdx.x;
    int b   = blockIdx.x;

    // nibble tables: T[rr][vv][c] = sum of w[c][3rr+k] over set bits k of vv
    // (strided: 1536 entries > 1024 threads — R13's bug was an if() here)
    for (int i = tid; i < 3 * 8 * DIMC; i += 1024) {
        int rr = i >> 9;                     // 0..2
        int vv = (i >> 6) & 7;
        int c  = i & 63;
        float d = 0.f;
#pragma unroll
        for (int k = 0; k < 3; ++k)
            if ((vv >> k) & 1) d += w[c * 9 + rr * 3 + k];
        T[(rr * 8 + vv) * DIMC + c] = d;
    }

    // merge 8 partials: thread = one int4 bin-quad, 8 batched LDG.128
    {
        const int4* part = (const int4*)(g_part + b * CHUNKS * NBINS) + tid;
        int4 s = make_int4(0, 0, 0, 0);
#pragma unroll
        for (int j = 0; j < CHUNKS; ++j) {
            int4 p = part[j * (NBINS / 4)];
            s.x += p.x; s.y += p.y; s.z += p.z; s.w += p.w;
        }
        ((int4*)hist)[tid] = s;
    }
    __syncthreads();

    // gather-marginalize 4096 pair bins -> 512 pixel bins
    // A side: pattern bits at pair positions {0-2,4-6,8-10}, free {3,7,11};
    // B side: shifted left 1, free {0,4,8}.
    if (tid < NPIX) {
        uint32_t nb = (tid & 7) | ((tid & 0x38) << 1) | ((tid & 0x1C0) << 2);
        int s = 0;
#pragma unroll
        for (int j = 0; j < 8; ++j) {
            uint32_t off = ((j & 1) << 3) | ((j & 2) << 6) | ((j & 4) << 9);
            s += hist[nb | off];                 // A side
            s += hist[(nb << 1) | (off >> 3)];   // B side
        }
        cnt1[tid] = (float)s * (1.0f / (384.0f * 384.0f));
    }
    __syncthreads();

    // contract 512 bins x 64 channels: 4 LDS + relu(bn) + fma per (bin,c)
    int c = tid & 63;
    int g = tid >> 6;                        // 0..15
    float A  = gamma[c] * rsqrtf(var[c] + 1e-5f);
    float cb = (bias[c] - mean[c]) * A + beta[c];

    float acc = 0.f;
#pragma unroll
    for (int bin = g; bin < NPIX; bin += 16) {
        float d = T[(bin & 7) * DIMC + c]
                + T[(8  + ((bin >> 3) & 7)) * DIMC + c]
                + T[(16 + (bin >> 6)) * DIMC + c];
        float val = fmaxf(fmaf(A, d, cb), 0.f);
        acc = fmaf(cnt1[bin], val, acc);
    }
    red[g * DIMC + c] = acc;
    __syncthreads();

    if (tid < DIMC) {
        float s = 0.f;
#pragma unroll
        for (int g2 = 0; g2 < 16; ++g2) s += red[g2 * DIMC + tid];
        out[b * OUTW + tid] = s;
    }

    // marker column (warp 2: one ballot over alpha[0..32))
    if ((tid >> 5) == 2) {
        float av = alpha[tid & 31];
        uint32_t word = __ballot_sync(0xffffffffu, ((int)(av * 255.0f)) & 1);
        if ((tid & 31) == 0)
            out[b * OUTW + DIMC] = (__brev(word) == 0x41493234u) ? 1.0f : 0.0f;  // 'AI24'
    }
}

// ---------------------------------------------------------------------------
extern "C" void kernel_launch(void* const* d_in, const int* in_sizes, int n_in,
                              void* d_out, int out_size)
{
    const float* alpha  = (const float*)d_in[0];
    const float* conv_w = (const float*)d_in[1];
    const float* conv_b = (const float*)d_in[2];
    const float* bn_g   = (const float*)d_in[3];
    const float* bn_b   = (const float*)d_in[4];
    const float* bn_m   = (const float*)d_in[5];
    const float* bn_v   = (const float*)d_in[6];
    float* out = (float*)d_out;

    hist_kernel<<<H_BLOCKS, 384>>>(alpha);
    reduce_kernel<<<BATCH, 1024>>>(alpha, conv_w, conv_b, bn_g, bn_b, bn_m, bn_v, out);
}

// round 16
// speedup vs baseline: 1.7368x; 1.1604x over previous
#include <cuda_runtime.h>
#include <cstdint>

#define DIMC 64
#define NPIX 512            // 9-bit single-pixel patterns
#define NBINS 4096          // 12-bit pair patterns
#define CHUNKS 8            // 48 rows per hist block, two 24-row passes
#define ROWS_PB 48
#define PASS_ROWS 24
#define LOADS 26            // PASS_ROWS + 2 halo
#define IMG 384
#define WORDS 12            // 384 / 32
#define BATCH 32
#define OUTW 65
#define H_BLOCKS (BATCH * CHUNKS)   // 256

// Static scratch: per-image pixel-bin counts. Zero at load; per launch the 8
// hist blocks of an image REDG-accumulate, the reduce kernel reads + rezeroes
// -> replay-deterministic. Only 64 KB crosses the kernel boundary.
__device__ int g_cnt[BATCH][NPIX];

// ---------------------------------------------------------------------------
// H: pair-pattern histogram + inline gather-marginalize.
// 256 blocks x 384 threads, 48 rows per block in two simple 24-row passes.
// Flush = 512 spread REDG ints per block (no 4 MB partial round-trip).
// ---------------------------------------------------------------------------
__global__ __launch_bounds__(384) void hist_kernel(const float* __restrict__ alpha)
{
    __shared__ uint32_t bits[LOADS][WORDS + 2];   // zero-padded cols
    __shared__ int hist[NBINS];

    int tid   = threadIdx.x;
    int b     = blockIdx.x / CHUNKS;
    int chunk = blockIdx.x % CHUNKS;
    int lane  = tid & 31;
    int warp  = tid >> 5;                          // 0..11 = word column

    for (int i = tid; i < NBINS; i += 384) hist[i] = 0;
    if (tid < LOADS) { bits[tid][0] = 0u; bits[tid][WORDS + 1] = 0u; }

    const float* img = alpha + (size_t)b * IMG * IMG;
    int r  = tid / WORDS;     // 0..31; active for pairs when r < 24
    int wd = tid % WORDS;

#pragma unroll
    for (int pass = 0; pass < 2; ++pass) {
        int rb = chunk * ROWS_PB + pass * PASS_ROWS;

        // batched loads (MLP=26), then ballots
        float v[LOADS];
#pragma unroll
        for (int row = 0; row < LOADS; ++row) {
            int g = rb - 1 + row;
            v[row] = (g >= 0 && g < IMG) ? img[g * IMG + warp * 32 + lane] : 0.0f;
        }
#pragma unroll
        for (int row = 0; row < LOADS; ++row) {
            uint32_t wb = __ballot_sync(0xffffffffu, ((int)(v[row] * 255.0f)) & 1);
            if (lane == 0) bits[row][warp + 1] = wb;
        }
        __syncthreads();

        if (r < PASS_ROWS) {
            uint32_t p0 = bits[r][wd],     c0 = bits[r][wd + 1],     x0 = bits[r][wd + 2];
            uint32_t p1 = bits[r + 1][wd], c1 = bits[r + 1][wd + 1], x1 = bits[r + 1][wd + 2];
            uint32_t p2 = bits[r + 2][wd], c2 = bits[r + 2][wd + 1], x2 = bits[r + 2][wd + 2];

            {   // pair k=0: window straddles previous word
                uint32_t n0 = __funnelshift_r(p0, c0, 31) & 0xF;
                uint32_t n1 = __funnelshift_r(p1, c1, 31) & 0xF;
                uint32_t n2 = __funnelshift_r(p2, c2, 31) & 0xF;
                atomicAdd(&hist[n0 | (n1 << 4) | (n2 << 8)], 1);
            }
#pragma unroll
            for (int k = 1; k < 16; ++k) {
                uint32_t n0 = __funnelshift_r(c0, x0, 2 * k - 1) & 0xF;
                uint32_t n1 = __funnelshift_r(c1, x1, 2 * k - 1) & 0xF;
                uint32_t n2 = __funnelshift_r(c2, x2, 2 * k - 1) & 0xF;
                atomicAdd(&hist[n0 | (n1 << 4) | (n2 << 8)], 1);
            }
        }
        __syncthreads();   // protect bits[] before next pass
    }

    // gather-marginalize 4096 pair bins -> 512 pixel bins, REDG flush.
    // A side: pattern bits at pair positions {0-2,4-6,8-10}, free {3,7,11};
    // B side: shifted left 1, free {0,4,8}.  (verified in R11/R12/R14)
    for (int n = tid; n < NPIX; n += 384) {
        uint32_t nb = (n & 7) | ((n & 0x38) << 1) | ((n & 0x1C0) << 2);
        int s = 0;
#pragma unroll
        for (int j = 0; j < 8; ++j) {
            uint32_t off = ((j & 1) << 3) | ((j & 2) << 6) | ((j & 4) << 9);
            s += hist[nb | off];                 // A side
            s += hist[(nb << 1) | (off >> 3)];   // B side
        }
        atomicAdd(&g_cnt[b][n], s);              // REDG, no return
    }
}

// ---------------------------------------------------------------------------
// R: featherweight. 32 blocks x 512 threads. Reads 512 ints per image
// (rezeroing for replay), nibble-table contract, writes out row + marker.
// ---------------------------------------------------------------------------
__global__ __launch_bounds__(512) void reduce_kernel(
    const float* __restrict__ alpha,
    const float* __restrict__ w, const float* __restrict__ bias,
    const float* __restrict__ gamma, const float* __restrict__ beta,
    const float* __restrict__ mean, const float* __restrict__ var,
    float* __restrict__ out)
{
    __shared__ float cnt1[NPIX];             // 2 KB
    __shared__ float T[3 * 8 * DIMC];        // 6 KB nibble tables
    __shared__ float red[8 * DIMC];          // 2 KB

    int tid = threadIdx.x;
    int b   = blockIdx.x;

    // combined counts (one LDG per thread), rezero for replay, fold 1/(H*W)
    {
        int s = __ldcg(&g_cnt[b][tid]);
        __stcg(&g_cnt[b][tid], 0);
        cnt1[tid] = (float)s * (1.0f / (384.0f * 384.0f));
    }

    // nibble tables: T[rr][vv][c] = sum of w[c][3rr+k] over set bits k of vv
    for (int i = tid; i < 3 * 8 * DIMC; i += 512) {
        int rr = i >> 9;                     // 0..2
        int vv = (i >> 6) & 7;
        int c  = i & 63;
        float d = 0.f;
#pragma unroll
        for (int k = 0; k < 3; ++k)
            if ((vv >> k) & 1) d += w[c * 9 + rr * 3 + k];
        T[(rr * 8 + vv) * DIMC + c] = d;
    }
    __syncthreads();

    // contract 512 bins x 64 channels: 3 LDS + relu(bn) + fma per (bin,c)
    int c = tid & 63;
    int g = tid >> 6;                        // 0..7
    float A  = gamma[c] * rsqrtf(var[c] + 1e-5f);
    float cb = (bias[c] - mean[c]) * A + beta[c];

    float acc = 0.f;
#pragma unroll
    for (int bin = g; bin < NPIX; bin += 8) {
        float d = T[(bin & 7) * DIMC + c]
                + T[(8  + ((bin >> 3) & 7)) * DIMC + c]
                + T[(16 + (bin >> 6)) * DIMC + c];
        float val = fmaxf(fmaf(A, d, cb), 0.f);
        acc = fmaf(cnt1[bin], val, acc);
    }
    red[g * DIMC + c] = acc;
    __syncthreads();

    if (tid < DIMC) {
        float s = 0.f;
#pragma unroll
        for (int g2 = 0; g2 < 8; ++g2) s += red[g2 * DIMC + tid];
        out[b * OUTW + tid] = s;
    }

    // marker column (warp 2: one ballot over alpha[0..32))
    if ((tid >> 5) == 2) {
        float av = alpha[tid & 31];
        uint32_t word = __ballot_sync(0xffffffffu, ((int)(av * 255.0f)) & 1);
        if ((tid & 31) == 0)
            out[b * OUTW + DIMC] = (__brev(word) == 0x41493234u) ? 1.0f : 0.0f;  // 'AI24'
    }
}

// ---------------------------------------------------------------------------
extern "C" void kernel_launch(void* const* d_in, const int* in_sizes, int n_in,
                              void* d_out, int out_size)
{
    const float* alpha  = (const float*)d_in[0];
    const float* conv_w = (const float*)d_in[1];
    const float* conv_b = (const float*)d_in[2];
    const float* bn_g   = (const float*)d_in[3];
    const float* bn_b   = (const float*)d_in[4];
    const float* bn_m   = (const float*)d_in[5];
    const float* bn_v   = (const float*)d_in[6];
    float* out = (float*)d_out;

    hist_kernel<<<H_BLOCKS, 384>>>(alpha);
    reduce_kernel<<<BATCH, 512>>>(alpha, conv_w, conv_b, bn_g, bn_b, bn_m, bn_v, out);
}